// round 4
// baseline (speedup 1.0000x reference)
#include <cuda_runtime.h>
#include <cuda_fp16.h>
#include <cstdint>

// dw[s,t] = SCALE * sum_b nt[b,s] * ap[b,t]
// SCALE = (0.05*0.05 - 0.01*0.05) * 0.001 / 256 = 7.8125e-9
#define S_DIM 8192
#define T_DIM 8192
#define K_DIM 256

static constexpr float SCALE_F = 7.8125e-9f;

static constexpr int THREADS   = 256;
static constexpr int KC        = 64;          // K per pipeline chunk
static constexpr int NCHUNK    = K_DIM / KC;  // 4
static constexpr int PITCH     = 136;         // smem row pitch in halves (pad kills ldmatrix conflicts)
static constexpr int PITCHB    = PITCH * 2;   // 272 bytes
static constexpr int STAGE_OP  = KC * PITCHB; // 17408 B per operand per stage
static constexpr int STAGE_TOT = 2 * STAGE_OP;
static constexpr int NSTAGE    = 3;
static constexpr int SMEM_BYTES = NSTAGE * STAGE_TOT; // 104448

// fp16 copies of the two inputs (static device scratch; no runtime alloc)
__device__ __half g_nth[(size_t)K_DIM * S_DIM];
__device__ __half g_aph[(size_t)K_DIM * T_DIM];

// ---------------- convert pass: fp32 -> fp16 ----------------
__global__ void cvt_kernel(const float* __restrict__ a, const float* __restrict__ b) {
    const int N4 = K_DIM * S_DIM / 4;  // 524288 float4 per array
    int i = blockIdx.x * blockDim.x + threadIdx.x;
    const float4* src;
    __half2* dst;
    int j;
    if (i < N4)          { src = (const float4*)a; dst = (__half2*)g_nth; j = i; }
    else if (i < 2 * N4) { src = (const float4*)b; dst = (__half2*)g_aph; j = i - N4; }
    else return;
    float4 v = src[j];
    dst[2 * j]     = __floats2half2_rn(v.x, v.y);
    dst[2 * j + 1] = __floats2half2_rn(v.z, v.w);
}

// ---------------- GEMM helpers ----------------
__device__ __forceinline__ uint32_t smem_u32(const void* p) {
    uint32_t a;
    asm("{ .reg .u64 t; cvta.to.shared.u64 t, %1; cvt.u32.u64 %0, t; }" : "=r"(a) : "l"(p));
    return a;
}

__device__ __forceinline__ void cp16(uint32_t s, const void* g) {
    asm volatile("cp.async.cg.shared.global [%0], [%1], 16;" :: "r"(s), "l"(g));
}

__device__ __forceinline__ void ldmx4t(uint32_t* d, uint32_t addr) {
    asm volatile("ldmatrix.sync.aligned.m8n8.x4.trans.shared.b16 {%0,%1,%2,%3}, [%4];"
                 : "=r"(d[0]), "=r"(d[1]), "=r"(d[2]), "=r"(d[3]) : "r"(addr));
}

__device__ __forceinline__ void mma16816(float* d, const uint32_t* a, uint32_t b0, uint32_t b1) {
    asm volatile(
        "mma.sync.aligned.m16n8k16.row.col.f32.f16.f16.f32 "
        "{%0,%1,%2,%3}, {%4,%5,%6,%7}, {%8,%9}, {%0,%1,%2,%3};"
        : "+f"(d[0]), "+f"(d[1]), "+f"(d[2]), "+f"(d[3])
        : "r"(a[0]), "r"(a[1]), "r"(a[2]), "r"(a[3]), "r"(b0), "r"(b1));
}

// ---------------- GEMM: C[8192,8192] = SCALE * A^T(256x8192) B(256x8192) ----------------
__global__ __launch_bounds__(THREADS, 2)
void stdp_gemm_kernel(float* __restrict__ out) {
    extern __shared__ __align__(16) char smem[];
    const uint32_t sb = smem_u32(smem);
    const int tid = threadIdx.x;
    const int bm = blockIdx.x;   // M tile (fast dim: a wave shares B tiles in L2)
    const int bn = blockIdx.y;

    const __half* __restrict__ A = g_nth;  // [k][m], m contiguous
    const __half* __restrict__ B = g_aph;  // [k][n], n contiguous

    const size_t a_g0 = (size_t)bm * 128;
    const size_t b_g0 = (size_t)bn * 128;

    // per-thread cp.async assignment: 4 (row,seg) chunks per operand per stage
    int rowv[4], segv[4];
#pragma unroll
    for (int i = 0; i < 4; i++) {
        int cc = tid + i * THREADS;
        rowv[i] = cc >> 4;
        segv[i] = cc & 15;
    }

#define LOAD_STAGE(st, k0)                                                        \
    do {                                                                          \
        uint32_t sbase = sb + (uint32_t)(st) * STAGE_TOT;                         \
        _Pragma("unroll")                                                         \
        for (int i = 0; i < 4; i++) {                                             \
            uint32_t so = (uint32_t)(rowv[i] * PITCHB + segv[i] * 16);            \
            const __half* ga = A + (size_t)((k0) + rowv[i]) * S_DIM + a_g0 + segv[i] * 8; \
            const __half* gb = B + (size_t)((k0) + rowv[i]) * T_DIM + b_g0 + segv[i] * 8; \
            cp16(sbase + so, ga);                                                 \
            cp16(sbase + STAGE_OP + so, gb);                                      \
        }                                                                         \
    } while (0)

    LOAD_STAGE(0, 0);
    asm volatile("cp.async.commit_group;" ::: "memory");
    LOAD_STAGE(1, KC);
    asm volatile("cp.async.commit_group;" ::: "memory");

    const int warp = tid >> 5, lane = tid & 31;
    const int wm = warp & 1;        // 0..1 -> m offset 0/64
    const int wn = warp >> 1;       // 0..3 -> n offset 0/32/64/96
    const int tile = lane >> 3, r = lane & 7;

    // ldmatrix.x4.trans lane offsets (bytes within stage), source layout [k][m|n]
    // A reg order: (m0-7,k0-7)(m8-15,k0-7)(m0-7,k8-15)(m8-15,k8-15)
    const uint32_t a_off = (uint32_t)((((tile >> 1) * 8 + r) * PITCHB) + (tile & 1) * 16 + wm * 64 * 2);
    // B reg order: (n0-7,k0-7)(n0-7,k8-15)(n8-15,k0-7)(n8-15,k8-15)
    const uint32_t b_off = (uint32_t)((((tile & 1) * 8 + r) * PITCHB) + (tile >> 1) * 16 + wn * 32 * 2)
                           + (uint32_t)STAGE_OP;

    float acc[4][4][4];
#pragma unroll
    for (int mi = 0; mi < 4; mi++)
#pragma unroll
        for (int nj = 0; nj < 4; nj++)
#pragma unroll
            for (int q = 0; q < 4; q++) acc[mi][nj][q] = 0.f;

    for (int c = 0; c < NCHUNK; c++) {
        asm volatile("cp.async.wait_group 1;" ::: "memory");
        __syncthreads();
        if (c + 2 < NCHUNK) LOAD_STAGE((c + 2) % NSTAGE, (c + 2) * KC);
        asm volatile("cp.async.commit_group;" ::: "memory");

        const uint32_t stbase = sb + (uint32_t)(c % NSTAGE) * STAGE_TOT;
#pragma unroll
        for (int ks = 0; ks < KC / 16; ks++) {
            const uint32_t ka = stbase + (uint32_t)(ks * 16 * PITCHB) + a_off;
            const uint32_t kb = stbase + (uint32_t)(ks * 16 * PITCHB) + b_off;
            uint32_t af[4][4], bf[2][4];
#pragma unroll
            for (int mi = 0; mi < 4; mi++) ldmx4t(af[mi], ka + mi * 32);
#pragma unroll
            for (int nb = 0; nb < 2; nb++) ldmx4t(bf[nb], kb + nb * 32);
#pragma unroll
            for (int mi = 0; mi < 4; mi++)
#pragma unroll
                for (int nj = 0; nj < 4; nj++)
                    mma16816(acc[mi][nj], af[mi],
                             bf[nj >> 1][(nj & 1) * 2], bf[nj >> 1][(nj & 1) * 2 + 1]);
        }
    }

    // ---------------- epilogue: scale + fp32 stores ----------------
    const int gr = lane >> 2, cq = lane & 3;
    const size_t row0 = (size_t)bm * 128 + wm * 64 + gr;
    const int col0 = bn * 128 + wn * 32 + cq * 2;
#pragma unroll
    for (int mi = 0; mi < 4; mi++) {
#pragma unroll
        for (int nj = 0; nj < 4; nj++) {
            float2 v0 = make_float2(acc[mi][nj][0] * SCALE_F, acc[mi][nj][1] * SCALE_F);
            float2 v1 = make_float2(acc[mi][nj][2] * SCALE_F, acc[mi][nj][3] * SCALE_F);
            *(float2*)(out + (row0 + mi * 16) * T_DIM + col0 + nj * 8) = v0;
            *(float2*)(out + (row0 + mi * 16 + 8) * T_DIM + col0 + nj * 8) = v1;
        }
    }
#undef LOAD_STAGE
}

extern "C" void kernel_launch(void* const* d_in, const int* in_sizes, int n_in,
                              void* d_out, int out_size) {
    const float* nt = (const float*)d_in[0];  // neurotransmitters (256, 8192)
    const float* ap = (const float*)d_in[2];  // action_potential  (256, 8192)
    float* out = (float*)d_out;               // (8192, 8192) fp32

    // pass 1: fp32 -> fp16 (both inputs), 1,048,576 threads
    cvt_kernel<<<(2 * K_DIM * S_DIM / 4 + 255) / 256, 256>>>(nt, ap);

    // pass 2: tensor-core GEMM
    cudaFuncSetAttribute(stdp_gemm_kernel,
                         cudaFuncAttributeMaxDynamicSharedMemorySize, SMEM_BYTES);
    dim3 grid(S_DIM / 128, T_DIM / 128);  // (64, 64)
    stdp_gemm_kernel<<<grid, THREADS, SMEM_BYTES>>>(out);
}